// round 14
// baseline (speedup 1.0000x reference)
#include <cuda_runtime.h>
#include <cuda_bf16.h>
#include <math.h>
#include <stdint.h>

#define L 40
#define B 16
#define VSZ 10000
#define FDIM 512
#define HDIM 256
#define NPAIR 780
#define NROWS ((NPAIR + 1) * B)     // 12496
#define NPADROWS 12544              // 49 * 256
#define MTILE 256
#define NTILE 128
#define NMT (NPADROWS / MTILE)      // 49
#define NT_N 79                     // ceil(10000/128)
#define YS 3                        // N-splits

#define DP_SMEM_BYTES ((L * L * B + 2 * NPAIR * B) * 4)   // 202,240 B

// word MMA smem layout (bytes)
#define PITCH 264                    // halves per row (256 + 8 pad)
#define SM_A 0                       // 256 * 264 * 2 = 135168
#define SM_B 135168                  // 128 * 264 * 2 = 67584
#define SM_BIAS 202752               // 128 f32
#define SM_TGT  203264               // 256 i32
#define SM_RED  204288               // 256*4 f32 = 4096
#define SM_PIJ  208384               // 16 int2 = 128
#define WORD_SMEM (SM_PIJ + 128)     // 208512

// prep kernel grid partition (hid branch fused into wordmma)
#define PREP_TPAIR 780
#define PREP_WCONV 2528              // 8 k-tiles x 316 n-tiles
#define PREP_GRID  (PREP_TPAIR + PREP_WCONV)

// ---------------- device scratch ----------------
__device__ float g_A1[L * B * HDIM];
__device__ float g_A2[L * B * HDIM];
__device__ float g_B1[L * B * HDIM];
__device__ float g_B2[L * B * HDIM];
__device__ float g_SH[NPAIR * B];
__device__ float g_RE[NPAIR * B];
__device__ __nv_bfloat16 g_Wb[NT_N * NTILE * HDIM];  // bf16 Ww2 transposed [n][k]
__device__ float g_PS[YS * NPADROWS];                // partial sum-of-exp
__device__ float g_TG[NPADROWS];                     // target logit

__device__ __forceinline__ void decode_pair(int p, int& i, int& j) {
    int ii = 0;
    while (p >= (L - 1) - ii) { p -= (L - 1) - ii; ++ii; }
    i = ii;
    j = ii + 1 + p;
}
__device__ __forceinline__ int pair_index(int i, int k) {
    return i * (L - 1) - (i * (i - 1)) / 2 + (k - i - 1);
}
__device__ __forceinline__ float logsig(float x) {
    return fminf(x, 0.f) - log1pf(__expf(-fabsf(x)));
}
__device__ __forceinline__ uint32_t smem_u32(const void* p) {
    uint32_t a;
    asm("{ .reg .u64 t; cvta.to.shared.u64 t, %1; cvt.u32.u64 %0, t; }" : "=r"(a) : "l"(p));
    return a;
}

#define LDSM_X4(r0, r1, r2, r3, addr)                                         \
    asm volatile("ldmatrix.sync.aligned.m8n8.x4.shared.b16 {%0,%1,%2,%3}, [%4];" \
                 : "=r"(r0), "=r"(r1), "=r"(r2), "=r"(r3) : "r"(addr))

#define MMA_BF16(d, a, b0v, b1v)                                              \
    asm volatile("mma.sync.aligned.m16n8k16.row.col.f32.bf16.bf16.f32 "       \
                 "{%0,%1,%2,%3}, {%4,%5,%6,%7}, {%8,%9}, {%0,%1,%2,%3};"      \
                 : "+f"((d)[0]), "+f"((d)[1]), "+f"((d)[2]), "+f"((d)[3])     \
                 : "r"((a)[0]), "r"((a)[1]), "r"((a)[2]), "r"((a)[3]),        \
                   "r"(b0v), "r"(b1v))

// ---------------- 1) projection GEMMs ----------------
__global__ void proj_kernel(const float* __restrict__ h,
                            const float* __restrict__ Wt1,
                            const float* __restrict__ Ww1) {
    __shared__ float As[16][65];
    __shared__ float Bs[16][65];

    int which = blockIdx.z;
    const float* W = (which < 2) ? Ww1 : Wt1;
    const float* Wbase = W + ((which & 1) ? FDIM * HDIM : 0);
    float* C = (which == 0) ? g_A1 : (which == 1) ? g_A2 : (which == 2) ? g_B1 : g_B2;

    int tx = threadIdx.x;
    int m0 = blockIdx.x * 64;
    int n0 = blockIdx.y * 64;
    int tm = (tx >> 4) * 4;
    int tn = (tx & 15) * 4;

    float acc[4][4];
#pragma unroll
    for (int a = 0; a < 4; a++)
#pragma unroll
        for (int c = 0; c < 4; c++) acc[a][c] = 0.f;

    for (int k0 = 0; k0 < FDIM; k0 += 16) {
#pragma unroll
        for (int l = tx; l < 64 * 16; l += 256) {
            int mm = l >> 4, kk = l & 15;
            As[kk][mm] = h[(m0 + mm) * FDIM + k0 + kk];
        }
#pragma unroll
        for (int l = tx; l < 16 * 64; l += 256) {
            int kk = l >> 6, nn = l & 63;
            Bs[kk][nn] = Wbase[(k0 + kk) * HDIM + n0 + nn];
        }
        __syncthreads();
#pragma unroll
        for (int kk = 0; kk < 16; ++kk) {
            float a0 = As[kk][tm], a1 = As[kk][tm + 1], a2 = As[kk][tm + 2], a3 = As[kk][tm + 3];
            float b0 = Bs[kk][tn], b1 = Bs[kk][tn + 1], b2 = Bs[kk][tn + 2], b3 = Bs[kk][tn + 3];
            acc[0][0] = fmaf(a0, b0, acc[0][0]); acc[0][1] = fmaf(a0, b1, acc[0][1]);
            acc[0][2] = fmaf(a0, b2, acc[0][2]); acc[0][3] = fmaf(a0, b3, acc[0][3]);
            acc[1][0] = fmaf(a1, b0, acc[1][0]); acc[1][1] = fmaf(a1, b1, acc[1][1]);
            acc[1][2] = fmaf(a1, b2, acc[1][2]); acc[1][3] = fmaf(a1, b3, acc[1][3]);
            acc[2][0] = fmaf(a2, b0, acc[2][0]); acc[2][1] = fmaf(a2, b1, acc[2][1]);
            acc[2][2] = fmaf(a2, b2, acc[2][2]); acc[2][3] = fmaf(a2, b3, acc[2][3]);
            acc[3][0] = fmaf(a3, b0, acc[3][0]); acc[3][1] = fmaf(a3, b1, acc[3][1]);
            acc[3][2] = fmaf(a3, b2, acc[3][2]); acc[3][3] = fmaf(a3, b3, acc[3][3]);
        }
        __syncthreads();
    }
#pragma unroll
    for (int a = 0; a < 4; a++)
#pragma unroll
        for (int c = 0; c < 4; c++)
            C[(m0 + tm + a) * HDIM + n0 + tn + c] = acc[a][c];
}

// ---------------- 2) fused prep: tpair | wconv (grid-partitioned) -----------
__global__ void prep_kernel(const float* __restrict__ bt1,
                            const float* __restrict__ Wt2,
                            const float* __restrict__ bt2,
                            const float* __restrict__ Ww2) {
    __shared__ float t[32][33];
    int blk = blockIdx.x;
    int tid = threadIdx.x;

    if (blk < PREP_TPAIR) {
        int p = blk;
        int wid = tid >> 5, lane = tid & 31;
        int i, j;
        decode_pair(p, i, j);
#pragma unroll
        for (int sub = 0; sub < 2; ++sub) {
            int b = wid * 2 + sub;
            const float* r1 = g_B1 + (i * B + b) * HDIM;
            const float* r2 = g_B2 + (j * B + b) * HDIM;
            float acc = 0.f;
#pragma unroll
            for (int hh = lane; hh < HDIM; hh += 32) {
                float hv = tanhf(r1[hh] + r2[hh] + bt1[hh]);
                acc = fmaf(hv, Wt2[hh], acc);
            }
            acc += __shfl_xor_sync(~0u, acc, 16);
            acc += __shfl_xor_sync(~0u, acc, 8);
            acc += __shfl_xor_sync(~0u, acc, 4);
            acc += __shfl_xor_sync(~0u, acc, 2);
            acc += __shfl_xor_sync(~0u, acc, 1);
            if (lane == 0) {
                float tt = acc + bt2[0];
                g_SH[p * B + b] = logsig(-tt);
                g_RE[p * B + b] = logsig(tt);
            }
        }
    } else {
        int tile = blk - PREP_TPAIR;
        int kt = tile & 7;
        int nt = tile >> 3;
        int tx = tid & 31, ty0 = tid >> 5;
#pragma unroll
        for (int rr = 0; rr < 4; ++rr) {
            int ty = ty0 + rr * 8;
            int k = kt * 32 + ty, n = nt * 32 + tx;
            t[ty][tx] = (n < VSZ) ? Ww2[k * VSZ + n] : 0.f;
        }
        __syncthreads();
#pragma unroll
        for (int rr = 0; rr < 4; ++rr) {
            int ty = ty0 + rr * 8;
            int n2 = nt * 32 + ty, k2 = kt * 32 + tx;
            g_Wb[n2 * HDIM + k2] = __float2bfloat16(t[tx][ty]);
        }
    }
}

// ---------------- 3) word GEMM: fused hidden-tanh + mma.sync bf16 + softmax --
__global__ __launch_bounds__(512)
void wordmma_kernel(const float* __restrict__ bw2,
                    const float* __restrict__ bw1,
                    const int* __restrict__ sentence) {
    extern __shared__ char smem[];
    uint32_t sb = smem_u32(smem);
    float* bias_s = (float*)(smem + SM_BIAS);
    int*   tgt_s  = (int*)(smem + SM_TGT);
    float* red_s  = (float*)(smem + SM_RED);
    int2*  pij_s  = (int2*)(smem + SM_PIJ);

    int tid = threadIdx.x;                 // 512
    int wid = tid >> 5, lane = tid & 31;
    int tq = lane & 3, gid = lane >> 2;
    int mt = blockIdx.x, ys = blockIdx.y;
    int warp_m = (wid & 3) * 64;           // 4 m-groups
    int warp_n = (wid >> 2) * 32;          // 4 n-groups

    // stage pair (i,j) for the 16 pairs of this m-tile
    if (tid < 16) {
        int p = mt * 16 + tid;
        int pi = 0, pj = 0;
        if (p < NPAIR) decode_pair(p, pi, pj);
        else if (p > NPAIR) pi = -1;       // pad rows -> zero hidden
        pij_s[tid] = make_int2(pi, pj);
    }
    __syncthreads();

    // targets
    if (tid < 256) {
        int p = mt * 16 + (tid >> 4);
        int bb = tid & 15;
        int2 pij = pij_s[tid >> 4];
        int tg = 0;
        if (p == NPAIR) tg = sentence[1 * B + bb];
        else if (p < NPAIR) {
            int j1 = (pij.y + 1 < L) ? (pij.y + 1) : (L - 1);
            tg = sentence[j1 * B + bb];
        }
        tgt_s[tid] = tg;
    }

    // fused hidden: A tile = tanh(A1[i] + A2[j] + bw1) -> bf16 smem
    for (int idx = tid; idx < 256 * 128; idx += 512) {
        int r = idx >> 7;                  // row 0..255
        int h2 = (idx & 127) * 2;          // even h offset
        int2 pij = pij_s[r >> 4];
        int bb = r & 15;
        uint32_t packed = 0;
        if (pij.x >= 0) {
            float2 a1 = *(const float2*)(g_A1 + ((size_t)pij.x * B + bb) * HDIM + h2);
            float2 a2 = *(const float2*)(g_A2 + ((size_t)pij.y * B + bb) * HDIM + h2);
            float2 bv = *(const float2*)(bw1 + h2);
            __nv_bfloat16 lo = __float2bfloat16(tanhf(a1.x + a2.x + bv.x));
            __nv_bfloat16 hi = __float2bfloat16(tanhf(a1.y + a2.y + bv.y));
            packed = (uint32_t)(*(uint16_t*)&lo) | ((uint32_t)(*(uint16_t*)&hi) << 16);
        }
        *(uint32_t*)(smem + SM_A + (r * PITCH + h2) * 2) = packed;
    }

    float rs[4][2];
#pragma unroll
    for (int mi = 0; mi < 4; ++mi) { rs[mi][0] = 0.f; rs[mi][1] = 0.f; }

    int nt0 = (ys * NT_N) / YS, nt1 = ((ys + 1) * NT_N) / YS;

    // prologue: prefetch first B tile into registers (8 x uint4 per thread)
    uint4 pre[8];
    {
        const __nv_bfloat16* wb = g_Wb + (size_t)nt0 * NTILE * HDIM;
#pragma unroll
        for (int u = 0; u < 8; ++u) {
            int idx = tid + u * 512;
            int r = idx >> 5, seg = idx & 31;
            pre[u] = *(const uint4*)(wb + r * HDIM + seg * 8);
        }
    }

    for (int nt = nt0; nt < nt1; ++nt) {
        int n0 = nt * NTILE;
        __syncthreads();    // previous iter's smem B reads done (also orders A stores)
#pragma unroll
        for (int u = 0; u < 8; ++u) {
            int idx = tid + u * 512;
            int r = idx >> 5, seg = idx & 31;
            *(uint4*)(smem + SM_B + (r * PITCH + seg * 8) * 2) = pre[u];
        }
        if (tid < 128) {
            int col = n0 + tid;
            bias_s[tid] = (col < VSZ) ? bw2[col] : 0.f;
        }
        __syncthreads();

        // prefetch next B tile into registers (overlaps with MMA below)
        if (nt + 1 < nt1) {
            const __nv_bfloat16* wb = g_Wb + (size_t)(nt + 1) * NTILE * HDIM;
#pragma unroll
            for (int u = 0; u < 8; ++u) {
                int idx = tid + u * 512;
                int r = idx >> 5, seg = idx & 31;
                pre[u] = *(const uint4*)(wb + r * HDIM + seg * 8);
            }
        }

        float d[4][4][4];
#pragma unroll
        for (int mi = 0; mi < 4; ++mi)
#pragma unroll
            for (int ni = 0; ni < 4; ++ni)
#pragma unroll
                for (int r = 0; r < 4; ++r) d[mi][ni][r] = 0.f;

#pragma unroll
        for (int ks = 0; ks < 16; ++ks) {
            int k0 = ks * 16;
            uint32_t a[4][4];
#pragma unroll
            for (int mi = 0; mi < 4; ++mi) {
                uint32_t row = warp_m + mi * 16 + (lane & 15);
                uint32_t col = k0 + ((lane >> 4) << 3);
                uint32_t ad = sb + SM_A + (row * PITCH + col) * 2;
                LDSM_X4(a[mi][0], a[mi][1], a[mi][2], a[mi][3], ad);
            }
#pragma unroll
            for (int nq = 0; nq < 2; ++nq) {
                uint32_t nrow = warp_n + nq * 16 + (lane & 7) + ((lane >> 4) << 3);
                uint32_t col = k0 + (((lane >> 3) & 1) << 3);
                uint32_t bd = sb + SM_B + (nrow * PITCH + col) * 2;
                uint32_t bfr[4];
                LDSM_X4(bfr[0], bfr[1], bfr[2], bfr[3], bd);
#pragma unroll
                for (int mi = 0; mi < 4; ++mi) {
                    MMA_BF16(d[mi][nq * 2 + 0], a[mi], bfr[0], bfr[1]);
                    MMA_BF16(d[mi][nq * 2 + 1], a[mi], bfr[2], bfr[3]);
                }
            }
        }

        // epilogue: bias + exp-sum + target gather
#pragma unroll
        for (int mi = 0; mi < 4; ++mi) {
            int r0 = warp_m + mi * 16 + gid;
            int r1 = r0 + 8;
            int t0 = tgt_s[r0], t1 = tgt_s[r1];
            int grow0 = mt * MTILE + r0, grow1 = mt * MTILE + r1;
            float acc0 = 0.f, acc1 = 0.f;
#pragma unroll
            for (int ni = 0; ni < 4; ++ni) {
                int cl = warp_n + ni * 8 + tq * 2;
                int colb = n0 + cl;
                float bia0 = bias_s[cl], bia1 = bias_s[cl + 1];
                float v0 = d[mi][ni][0] + bia0;
                float v1 = d[mi][ni][1] + bia1;
                float v2 = d[mi][ni][2] + bia0;
                float v3 = d[mi][ni][3] + bia1;
                if (colb < VSZ) {
                    acc0 += __expf(v0);
                    acc1 += __expf(v2);
                    if (colb == t0) g_TG[grow0] = v0;
                    if (colb == t1) g_TG[grow1] = v2;
                }
                if (colb + 1 < VSZ) {
                    acc0 += __expf(v1);
                    acc1 += __expf(v3);
                    if (colb + 1 == t0) g_TG[grow0] = v1;
                    if (colb + 1 == t1) g_TG[grow1] = v3;
                }
            }
            rs[mi][0] += acc0;
            rs[mi][1] += acc1;
        }
    }

    // reduce rowsum across the 4 lanes of each row group
#pragma unroll
    for (int mi = 0; mi < 4; ++mi) {
#pragma unroll
        for (int hh = 0; hh < 2; ++hh) {
            float x = rs[mi][hh];
            x += __shfl_xor_sync(~0u, x, 1);
            x += __shfl_xor_sync(~0u, x, 2);
            if (tq == 0) {
                int row_l = warp_m + mi * 16 + gid + hh * 8;
                red_s[row_l * 4 + (wid >> 2)] = x;
            }
        }
    }
    __syncthreads();
    if (tid < 256) {
        float s = red_s[tid * 4 + 0] + red_s[tid * 4 + 1]
                + red_s[tid * 4 + 2] + red_s[tid * 4 + 3];
        g_PS[ys * NPADROWS + mt * MTILE + tid] = s;
    }
}

// ---------------- 4) CKY DP (fused fixup; strength-reduced; two-chain LSE) ---
__global__ void dp_kernel(float* __restrict__ out) {
    extern __shared__ float sm[];
    float* T_s   = sm;
    float* SHW_s = sm + L * L * B;
    float* RE_s  = SHW_s + NPAIR * B;

    int tid = threadIdx.x;                 // 640
    int b = tid & 15, i = tid >> 4;

    // fused fixup: WLP = target - log(sum of 3 partials), folded into SHW
    for (int idx = tid; idx < NPAIR * B; idx += 640) {
        float s = g_PS[idx] + g_PS[NPADROWS + idx] + g_PS[2 * NPADROWS + idx];
        float wlp = g_TG[idx] - logf(s);
        SHW_s[idx] = g_SH[idx] + wlp;
        RE_s[idx]  = g_RE[idx];
    }
    if (i == 0) {
        int r = NPAIR * B + b;
        float s = g_PS[r] + g_PS[NPADROWS + r] + g_PS[2 * NPADROWS + r];
        T_s[(0 * L + 1) * B + b] = g_TG[r] - logf(s);
    } else if (i >= 1 && i <= 38) {
        T_s[(i * L + (i + 1)) * B + b] = 0.f;
    }
    __syncthreads();

    // precompute per-thread invariants
    int pik0 = pair_index(i, i + 1);           // advances +1 per k
    for (int gap = 2; gap <= L - 1; ++gap) {
        int n_i = L - gap;
        int j = i + gap;
        if (i < n_i) {
            // strength-reduced operand indices
            const float* pT1 = T_s + (i * L + (i + 1)) * B + b;     // +B per k
            const float* pT2 = T_s + ((i + 1) * L + j) * B + b;     // +L*B per k
            const float* pSH = SHW_s + pik0 * B + b;                // +B per k
            int reIdx = pair_index(i + 1, j) * B + b;
            int dre = (37 - i) * B;                                  // then -B per k

            float m0 = -1e30f, s0 = 0.f, m1 = -1e30f, s1 = 0.f;
            int nk = gap - 1;
            int kk = 0;
            for (; kk + 1 < nk; kk += 2) {
                float sc0 = pT1[0] + pT2[0] + pSH[0] + RE_s[reIdx];
                reIdx += dre; dre -= B;
                float sc1 = pT1[B] + pT2[L * B] + pSH[B] + RE_s[reIdx];
                reIdx += dre; dre -= B;
                pT1 += 2 * B; pT2 += 2 * L * B; pSH += 2 * B;
                float mn0 = fmaxf(m0, sc0);
                s0 = fmaf(s0, __expf(m0 - mn0), __expf(sc0 - mn0));
                m0 = mn0;
                float mn1 = fmaxf(m1, sc1);
                s1 = fmaf(s1, __expf(m1 - mn1), __expf(sc1 - mn1));
                m1 = mn1;
            }
            if (kk < nk) {
                float sc0 = pT1[0] + pT2[0] + pSH[0] + RE_s[reIdx];
                float mn0 = fmaxf(m0, sc0);
                s0 = fmaf(s0, __expf(m0 - mn0), __expf(sc0 - mn0));
                m0 = mn0;
            }
            float mn = fmaxf(m0, m1);
            float ss = s0 * __expf(m0 - mn) + s1 * __expf(m1 - mn);
            T_s[(i * L + j) * B + b] = mn + logf(ss);
        }
        __syncthreads();
    }

    if (tid < B) out[tid] = T_s[(0 * L + (L - 1)) * B + tid];
}

// ---------------- launcher ----------------
extern "C" void kernel_launch(void* const* d_in, const int* in_sizes, int n_in,
                              void* d_out, int out_size) {
    const float* h        = (const float*)d_in[0];
    const int*   sentence = (const int*)d_in[1];
    const float* Wt1      = (const float*)d_in[2];
    const float* bt1      = (const float*)d_in[3];
    const float* Wt2      = (const float*)d_in[4];
    const float* bt2      = (const float*)d_in[5];
    const float* Ww1      = (const float*)d_in[6];
    const float* bw1      = (const float*)d_in[7];
    const float* Ww2      = (const float*)d_in[8];
    const float* bw2      = (const float*)d_in[9];
    float* out = (float*)d_out;

    static bool attr_set = false;
    if (!attr_set) {
        cudaFuncSetAttribute(dp_kernel, cudaFuncAttributeMaxDynamicSharedMemorySize,
                             DP_SMEM_BYTES);
        cudaFuncSetAttribute(wordmma_kernel, cudaFuncAttributeMaxDynamicSharedMemorySize,
                             WORD_SMEM);
        attr_set = true;
    }

    proj_kernel<<<dim3(10, 4, 4), 256>>>(h, Wt1, Ww1);
    prep_kernel<<<PREP_GRID, 256>>>(bt1, Wt2, bt2, Ww2);
    wordmma_kernel<<<dim3(NMT, YS), 512, WORD_SMEM>>>(bw2, bw1, sentence);
    dp_kernel<<<1, 640, DP_SMEM_BYTES>>>(out);
}

// round 15
// speedup vs baseline: 1.0262x; 1.0262x over previous
#include <cuda_runtime.h>
#include <cuda_bf16.h>
#include <math.h>
#include <stdint.h>

#define L 40
#define B 16
#define VSZ 10000
#define FDIM 512
#define HDIM 256
#define NPAIR 780
#define NROWS ((NPAIR + 1) * B)     // 12496
#define NPADROWS 12544              // 49 * 256
#define MTILE 256
#define NTILE 128
#define NMT (NPADROWS / MTILE)      // 49
#define NT_N 79                     // ceil(10000/128)
#define YS 3                        // N-splits

#define DP_SMEM_BYTES ((L * L * B + 2 * NPAIR * B) * 4)   // 202,240 B

// word MMA smem layout (bytes)
#define PITCH 264                    // halves per row (256 + 8 pad)
#define SM_A 0                       // 256 * 264 * 2 = 135168
#define SM_B 135168                  // 128 * 264 * 2 = 67584
#define SM_BIAS 202752               // 128 f32
#define SM_TGT  203264               // 256 i32
#define SM_RED  204288               // 256*4 f32 = 4096
#define SM_PIJ  208384               // 16 int2 = 128
#define WORD_SMEM (SM_PIJ + 128)     // 208512

// prep kernel grid partition (hid branch fused into wordmma)
#define PREP_TPAIR 780
#define PREP_WCONV 2528              // 8 k-tiles x 316 n-tiles
#define PREP_GRID  (PREP_TPAIR + PREP_WCONV)

// ---------------- device scratch ----------------
__device__ float g_A1[L * B * HDIM];
__device__ float g_A2[L * B * HDIM];
__device__ float g_B1[L * B * HDIM];
__device__ float g_B2[L * B * HDIM];
__device__ float g_SH[NPAIR * B];
__device__ float g_RE[NPAIR * B];
__device__ __nv_bfloat16 g_Wb[NT_N * NTILE * HDIM];  // bf16 Ww2 transposed [n][k]
__device__ float g_PS[YS * NPADROWS];                // partial sum-of-exp
__device__ float g_TG[NPADROWS];                     // target logit

__device__ __forceinline__ void decode_pair(int p, int& i, int& j) {
    int ii = 0;
    while (p >= (L - 1) - ii) { p -= (L - 1) - ii; ++ii; }
    i = ii;
    j = ii + 1 + p;
}
__device__ __forceinline__ int pair_index(int i, int k) {
    return i * (L - 1) - (i * (i - 1)) / 2 + (k - i - 1);
}
__device__ __forceinline__ float logsig(float x) {
    return fminf(x, 0.f) - log1pf(__expf(-fabsf(x)));
}
__device__ __forceinline__ uint32_t smem_u32(const void* p) {
    uint32_t a;
    asm("{ .reg .u64 t; cvta.to.shared.u64 t, %1; cvt.u32.u64 %0, t; }" : "=r"(a) : "l"(p));
    return a;
}

#define LDSM_X4(r0, r1, r2, r3, addr)                                         \
    asm volatile("ldmatrix.sync.aligned.m8n8.x4.shared.b16 {%0,%1,%2,%3}, [%4];" \
                 : "=r"(r0), "=r"(r1), "=r"(r2), "=r"(r3) : "r"(addr))

#define MMA_BF16(d, a, b0v, b1v)                                              \
    asm volatile("mma.sync.aligned.m16n8k16.row.col.f32.bf16.bf16.f32 "       \
                 "{%0,%1,%2,%3}, {%4,%5,%6,%7}, {%8,%9}, {%0,%1,%2,%3};"      \
                 : "+f"((d)[0]), "+f"((d)[1]), "+f"((d)[2]), "+f"((d)[3])     \
                 : "r"((a)[0]), "r"((a)[1]), "r"((a)[2]), "r"((a)[3]),        \
                   "r"(b0v), "r"(b1v))

// ---------------- 1) projection GEMMs ----------------
__global__ void proj_kernel(const float* __restrict__ h,
                            const float* __restrict__ Wt1,
                            const float* __restrict__ Ww1) {
    __shared__ float As[16][65];
    __shared__ float Bs[16][65];

    int which = blockIdx.z;
    const float* W = (which < 2) ? Ww1 : Wt1;
    const float* Wbase = W + ((which & 1) ? FDIM * HDIM : 0);
    float* C = (which == 0) ? g_A1 : (which == 1) ? g_A2 : (which == 2) ? g_B1 : g_B2;

    int tx = threadIdx.x;
    int m0 = blockIdx.x * 64;
    int n0 = blockIdx.y * 64;
    int tm = (tx >> 4) * 4;
    int tn = (tx & 15) * 4;

    float acc[4][4];
#pragma unroll
    for (int a = 0; a < 4; a++)
#pragma unroll
        for (int c = 0; c < 4; c++) acc[a][c] = 0.f;

    for (int k0 = 0; k0 < FDIM; k0 += 16) {
#pragma unroll
        for (int l = tx; l < 64 * 16; l += 256) {
            int mm = l >> 4, kk = l & 15;
            As[kk][mm] = h[(m0 + mm) * FDIM + k0 + kk];
        }
#pragma unroll
        for (int l = tx; l < 16 * 64; l += 256) {
            int kk = l >> 6, nn = l & 63;
            Bs[kk][nn] = Wbase[(k0 + kk) * HDIM + n0 + nn];
        }
        __syncthreads();
#pragma unroll
        for (int kk = 0; kk < 16; ++kk) {
            float a0 = As[kk][tm], a1 = As[kk][tm + 1], a2 = As[kk][tm + 2], a3 = As[kk][tm + 3];
            float b0 = Bs[kk][tn], b1 = Bs[kk][tn + 1], b2 = Bs[kk][tn + 2], b3 = Bs[kk][tn + 3];
            acc[0][0] = fmaf(a0, b0, acc[0][0]); acc[0][1] = fmaf(a0, b1, acc[0][1]);
            acc[0][2] = fmaf(a0, b2, acc[0][2]); acc[0][3] = fmaf(a0, b3, acc[0][3]);
            acc[1][0] = fmaf(a1, b0, acc[1][0]); acc[1][1] = fmaf(a1, b1, acc[1][1]);
            acc[1][2] = fmaf(a1, b2, acc[1][2]); acc[1][3] = fmaf(a1, b3, acc[1][3]);
            acc[2][0] = fmaf(a2, b0, acc[2][0]); acc[2][1] = fmaf(a2, b1, acc[2][1]);
            acc[2][2] = fmaf(a2, b2, acc[2][2]); acc[2][3] = fmaf(a2, b3, acc[2][3]);
            acc[3][0] = fmaf(a3, b0, acc[3][0]); acc[3][1] = fmaf(a3, b1, acc[3][1]);
            acc[3][2] = fmaf(a3, b2, acc[3][2]); acc[3][3] = fmaf(a3, b3, acc[3][3]);
        }
        __syncthreads();
    }
#pragma unroll
    for (int a = 0; a < 4; a++)
#pragma unroll
        for (int c = 0; c < 4; c++)
            C[(m0 + tm + a) * HDIM + n0 + tn + c] = acc[a][c];
}

// ---------------- 2) fused prep: tpair | wconv (grid-partitioned) -----------
__global__ void prep_kernel(const float* __restrict__ bt1,
                            const float* __restrict__ Wt2,
                            const float* __restrict__ bt2,
                            const float* __restrict__ Ww2) {
    __shared__ float t[32][33];
    int blk = blockIdx.x;
    int tid = threadIdx.x;

    if (blk < PREP_TPAIR) {
        int p = blk;
        int wid = tid >> 5, lane = tid & 31;
        int i, j;
        decode_pair(p, i, j);
#pragma unroll
        for (int sub = 0; sub < 2; ++sub) {
            int b = wid * 2 + sub;
            const float* r1 = g_B1 + (i * B + b) * HDIM;
            const float* r2 = g_B2 + (j * B + b) * HDIM;
            float acc = 0.f;
#pragma unroll
            for (int hh = lane; hh < HDIM; hh += 32) {
                float hv = tanhf(r1[hh] + r2[hh] + bt1[hh]);
                acc = fmaf(hv, Wt2[hh], acc);
            }
            acc += __shfl_xor_sync(~0u, acc, 16);
            acc += __shfl_xor_sync(~0u, acc, 8);
            acc += __shfl_xor_sync(~0u, acc, 4);
            acc += __shfl_xor_sync(~0u, acc, 2);
            acc += __shfl_xor_sync(~0u, acc, 1);
            if (lane == 0) {
                float tt = acc + bt2[0];
                g_SH[p * B + b] = logsig(-tt);
                g_RE[p * B + b] = logsig(tt);
            }
        }
    } else {
        int tile = blk - PREP_TPAIR;
        int kt = tile & 7;
        int nt = tile >> 3;
        int tx = tid & 31, ty0 = tid >> 5;
#pragma unroll
        for (int rr = 0; rr < 4; ++rr) {
            int ty = ty0 + rr * 8;
            int k = kt * 32 + ty, n = nt * 32 + tx;
            t[ty][tx] = (n < VSZ) ? Ww2[k * VSZ + n] : 0.f;
        }
        __syncthreads();
#pragma unroll
        for (int rr = 0; rr < 4; ++rr) {
            int ty = ty0 + rr * 8;
            int n2 = nt * 32 + ty, k2 = kt * 32 + tx;
            g_Wb[n2 * HDIM + k2] = __float2bfloat16(t[tx][ty]);
        }
    }
}

// ---------------- 3) word GEMM: fused hidden-tanh + mma.sync bf16 + softmax --
__global__ __launch_bounds__(512)
void wordmma_kernel(const float* __restrict__ bw2,
                    const float* __restrict__ bw1,
                    const int* __restrict__ sentence) {
    extern __shared__ char smem[];
    uint32_t sb = smem_u32(smem);
    float* bias_s = (float*)(smem + SM_BIAS);
    int*   tgt_s  = (int*)(smem + SM_TGT);
    float* red_s  = (float*)(smem + SM_RED);
    int2*  pij_s  = (int2*)(smem + SM_PIJ);

    int tid = threadIdx.x;                 // 512
    int wid = tid >> 5, lane = tid & 31;
    int tq = lane & 3, gid = lane >> 2;
    int mt = blockIdx.x, ys = blockIdx.y;
    int warp_m = (wid & 3) * 64;           // 4 m-groups
    int warp_n = (wid >> 2) * 32;          // 4 n-groups

    // stage pair (i,j) for the 16 pairs of this m-tile
    if (tid < 16) {
        int p = mt * 16 + tid;
        int pi = 0, pj = 0;
        if (p < NPAIR) decode_pair(p, pi, pj);
        else if (p > NPAIR) pi = -1;       // pad rows -> zero hidden
        pij_s[tid] = make_int2(pi, pj);
    }
    __syncthreads();

    // targets
    if (tid < 256) {
        int p = mt * 16 + (tid >> 4);
        int bb = tid & 15;
        int2 pij = pij_s[tid >> 4];
        int tg = 0;
        if (p == NPAIR) tg = sentence[1 * B + bb];
        else if (p < NPAIR) {
            int j1 = (pij.y + 1 < L) ? (pij.y + 1) : (L - 1);
            tg = sentence[j1 * B + bb];
        }
        tgt_s[tid] = tg;
    }

    // fused hidden: A tile = tanh(A1[i] + A2[j] + bw1) -> bf16 smem
    for (int idx = tid; idx < 256 * 128; idx += 512) {
        int r = idx >> 7;                  // row 0..255
        int h2 = (idx & 127) * 2;          // even h offset
        int2 pij = pij_s[r >> 4];
        int bb = r & 15;
        uint32_t packed = 0;
        if (pij.x >= 0) {
            float2 a1 = *(const float2*)(g_A1 + ((size_t)pij.x * B + bb) * HDIM + h2);
            float2 a2 = *(const float2*)(g_A2 + ((size_t)pij.y * B + bb) * HDIM + h2);
            float2 bv = *(const float2*)(bw1 + h2);
            __nv_bfloat16 lo = __float2bfloat16(tanhf(a1.x + a2.x + bv.x));
            __nv_bfloat16 hi = __float2bfloat16(tanhf(a1.y + a2.y + bv.y));
            packed = (uint32_t)(*(uint16_t*)&lo) | ((uint32_t)(*(uint16_t*)&hi) << 16);
        }
        *(uint32_t*)(smem + SM_A + (r * PITCH + h2) * 2) = packed;
    }

    float rs[4][2];
#pragma unroll
    for (int mi = 0; mi < 4; ++mi) { rs[mi][0] = 0.f; rs[mi][1] = 0.f; }

    int nt0 = (ys * NT_N) / YS, nt1 = ((ys + 1) * NT_N) / YS;

    // prologue: prefetch first B tile into registers (8 x uint4 per thread)
    uint4 pre[8];
    {
        const __nv_bfloat16* wb = g_Wb + (size_t)nt0 * NTILE * HDIM;
#pragma unroll
        for (int u = 0; u < 8; ++u) {
            int idx = tid + u * 512;
            int r = idx >> 5, seg = idx & 31;
            pre[u] = *(const uint4*)(wb + r * HDIM + seg * 8);
        }
    }

    for (int nt = nt0; nt < nt1; ++nt) {
        int n0 = nt * NTILE;
        __syncthreads();    // previous iter's smem B reads done (also orders A stores)
#pragma unroll
        for (int u = 0; u < 8; ++u) {
            int idx = tid + u * 512;
            int r = idx >> 5, seg = idx & 31;
            *(uint4*)(smem + SM_B + (r * PITCH + seg * 8) * 2) = pre[u];
        }
        if (tid < 128) {
            int col = n0 + tid;
            // poisoned pad bias: exp(v) == 0 for pad columns -> branch-free epilogue
            bias_s[tid] = (col < VSZ) ? bw2[col] : -1e30f;
        }
        __syncthreads();

        // prefetch next B tile into registers (overlaps with MMA below)
        if (nt + 1 < nt1) {
            const __nv_bfloat16* wb = g_Wb + (size_t)(nt + 1) * NTILE * HDIM;
#pragma unroll
            for (int u = 0; u < 8; ++u) {
                int idx = tid + u * 512;
                int r = idx >> 5, seg = idx & 31;
                pre[u] = *(const uint4*)(wb + r * HDIM + seg * 8);
            }
        }

        float d[4][4][4];
#pragma unroll
        for (int mi = 0; mi < 4; ++mi)
#pragma unroll
            for (int ni = 0; ni < 4; ++ni)
#pragma unroll
                for (int r = 0; r < 4; ++r) d[mi][ni][r] = 0.f;

#pragma unroll
        for (int ks = 0; ks < 16; ++ks) {
            int k0 = ks * 16;
            uint32_t a[4][4];
#pragma unroll
            for (int mi = 0; mi < 4; ++mi) {
                uint32_t row = warp_m + mi * 16 + (lane & 15);
                uint32_t col = k0 + ((lane >> 4) << 3);
                uint32_t ad = sb + SM_A + (row * PITCH + col) * 2;
                LDSM_X4(a[mi][0], a[mi][1], a[mi][2], a[mi][3], ad);
            }
#pragma unroll
            for (int nq = 0; nq < 2; ++nq) {
                uint32_t nrow = warp_n + nq * 16 + (lane & 7) + ((lane >> 4) << 3);
                uint32_t col = k0 + (((lane >> 3) & 1) << 3);
                uint32_t bd = sb + SM_B + (nrow * PITCH + col) * 2;
                uint32_t bfr[4];
                LDSM_X4(bfr[0], bfr[1], bfr[2], bfr[3], bd);
#pragma unroll
                for (int mi = 0; mi < 4; ++mi) {
                    MMA_BF16(d[mi][nq * 2 + 0], a[mi], bfr[0], bfr[1]);
                    MMA_BF16(d[mi][nq * 2 + 1], a[mi], bfr[2], bfr[3]);
                }
            }
        }

        // epilogue: bias + exp-sum + target gather (branch-free on validity)
#pragma unroll
        for (int mi = 0; mi < 4; ++mi) {
            int r0 = warp_m + mi * 16 + gid;
            int r1 = r0 + 8;
            int t0 = tgt_s[r0], t1 = tgt_s[r1];
            int grow0 = mt * MTILE + r0, grow1 = mt * MTILE + r1;
            float acc0 = 0.f, acc1 = 0.f;
#pragma unroll
            for (int ni = 0; ni < 4; ++ni) {
                int cl = warp_n + ni * 8 + tq * 2;
                int colb = n0 + cl;
                float bia0 = bias_s[cl], bia1 = bias_s[cl + 1];
                float v0 = d[mi][ni][0] + bia0;
                float v1 = d[mi][ni][1] + bia1;
                float v2 = d[mi][ni][2] + bia0;
                float v3 = d[mi][ni][3] + bia1;
                acc0 += __expf(v0) + __expf(v1);
                acc1 += __expf(v2) + __expf(v3);
                if (colb == t0) g_TG[grow0] = v0;
                if (colb + 1 == t0) g_TG[grow0] = v1;
                if (colb == t1) g_TG[grow1] = v2;
                if (colb + 1 == t1) g_TG[grow1] = v3;
            }
            rs[mi][0] += acc0;
            rs[mi][1] += acc1;
        }
    }

    // reduce rowsum across the 4 lanes of each row group
#pragma unroll
    for (int mi = 0; mi < 4; ++mi) {
#pragma unroll
        for (int hh = 0; hh < 2; ++hh) {
            float x = rs[mi][hh];
            x += __shfl_xor_sync(~0u, x, 1);
            x += __shfl_xor_sync(~0u, x, 2);
            if (tq == 0) {
                int row_l = warp_m + mi * 16 + gid + hh * 8;
                red_s[row_l * 4 + (wid >> 2)] = x;
            }
        }
    }
    __syncthreads();
    if (tid < 256) {
        float s = red_s[tid * 4 + 0] + red_s[tid * 4 + 1]
                + red_s[tid * 4 + 2] + red_s[tid * 4 + 3];
        g_PS[ys * NPADROWS + mt * MTILE + tid] = s;
    }
}

// ---------------- 4) CKY DP (fused fixup; strength-reduced; two-chain LSE) ---
__global__ void dp_kernel(float* __restrict__ out) {
    extern __shared__ float sm[];
    float* T_s   = sm;
    float* SHW_s = sm + L * L * B;
    float* RE_s  = SHW_s + NPAIR * B;

    int tid = threadIdx.x;                 // 640
    int b = tid & 15, i = tid >> 4;

    // fused fixup: WLP = target - log(sum of 3 partials), folded into SHW
    for (int idx = tid; idx < NPAIR * B; idx += 640) {
        float s = g_PS[idx] + g_PS[NPADROWS + idx] + g_PS[2 * NPADROWS + idx];
        float wlp = g_TG[idx] - __logf(s);
        SHW_s[idx] = g_SH[idx] + wlp;
        RE_s[idx]  = g_RE[idx];
    }
    if (i == 0) {
        int r = NPAIR * B + b;
        float s = g_PS[r] + g_PS[NPADROWS + r] + g_PS[2 * NPADROWS + r];
        T_s[(0 * L + 1) * B + b] = g_TG[r] - __logf(s);
    } else if (i >= 1 && i <= 38) {
        T_s[(i * L + (i + 1)) * B + b] = 0.f;
    }
    __syncthreads();

    // precompute per-thread invariants
    int pik0 = pair_index(i, i + 1);           // advances +1 per k
    for (int gap = 2; gap <= L - 1; ++gap) {
        int n_i = L - gap;
        int j = i + gap;
        if (i < n_i) {
            // strength-reduced operand indices
            const float* pT1 = T_s + (i * L + (i + 1)) * B + b;     // +B per k
            const float* pT2 = T_s + ((i + 1) * L + j) * B + b;     // +L*B per k
            const float* pSH = SHW_s + pik0 * B + b;                // +B per k
            int reIdx = pair_index(i + 1, j) * B + b;
            int dre = (37 - i) * B;                                  // then -B per k

            float m0 = -1e30f, s0 = 0.f, m1 = -1e30f, s1 = 0.f;
            int nk = gap - 1;
            int kk = 0;
            for (; kk + 1 < nk; kk += 2) {
                float sc0 = pT1[0] + pT2[0] + pSH[0] + RE_s[reIdx];
                reIdx += dre; dre -= B;
                float sc1 = pT1[B] + pT2[L * B] + pSH[B] + RE_s[reIdx];
                reIdx += dre; dre -= B;
                pT1 += 2 * B; pT2 += 2 * L * B; pSH += 2 * B;
                float mn0 = fmaxf(m0, sc0);
                s0 = fmaf(s0, __expf(m0 - mn0), __expf(sc0 - mn0));
                m0 = mn0;
                float mn1 = fmaxf(m1, sc1);
                s1 = fmaf(s1, __expf(m1 - mn1), __expf(sc1 - mn1));
                m1 = mn1;
            }
            if (kk < nk) {
                float sc0 = pT1[0] + pT2[0] + pSH[0] + RE_s[reIdx];
                float mn0 = fmaxf(m0, sc0);
                s0 = fmaf(s0, __expf(m0 - mn0), __expf(sc0 - mn0));
                m0 = mn0;
            }
            float mn = fmaxf(m0, m1);
            float ss = s0 * __expf(m0 - mn) + s1 * __expf(m1 - mn);
            T_s[(i * L + j) * B + b] = mn + __logf(ss);
        }
        __syncthreads();
    }

    if (tid < B) out[tid] = T_s[(0 * L + (L - 1)) * B + tid];
}

// ---------------- launcher ----------------
extern "C" void kernel_launch(void* const* d_in, const int* in_sizes, int n_in,
                              void* d_out, int out_size) {
    const float* h        = (const float*)d_in[0];
    const int*   sentence = (const int*)d_in[1];
    const float* Wt1      = (const float*)d_in[2];
    const float* bt1      = (const float*)d_in[3];
    const float* Wt2      = (const float*)d_in[4];
    const float* bt2      = (const float*)d_in[5];
    const float* Ww1      = (const float*)d_in[6];
    const float* bw1      = (const float*)d_in[7];
    const float* Ww2      = (const float*)d_in[8];
    const float* bw2      = (const float*)d_in[9];
    float* out = (float*)d_out;

    static bool attr_set = false;
    if (!attr_set) {
        cudaFuncSetAttribute(dp_kernel, cudaFuncAttributeMaxDynamicSharedMemorySize,
                             DP_SMEM_BYTES);
        cudaFuncSetAttribute(wordmma_kernel, cudaFuncAttributeMaxDynamicSharedMemorySize,
                             WORD_SMEM);
        attr_set = true;
    }

    proj_kernel<<<dim3(10, 4, 4), 256>>>(h, Wt1, Ww1);
    prep_kernel<<<PREP_GRID, 256>>>(bt1, Wt2, bt2, Ww2);
    wordmma_kernel<<<dim3(NMT, YS), 512, WORD_SMEM>>>(bw2, bw1, sentence);
    dp_kernel<<<1, 640, DP_SMEM_BYTES>>>(out);
}